// round 3
// baseline (speedup 1.0000x reference)
#include <cuda_runtime.h>
#include <cfloat>

// Shapes (fixed): enc (32,64,64,64) fp32 -> 131072 vectors of D=64; codebook (512,64) fp32.
#define DDIM   64
#define KCODE  512
#define KP     256            // code pairs
#define NTOT   8388608
#define NVEC   131072
#define TPB    384            // 12 warps/SM, reg cap 170
#define GRID   148
#define VPU    64             // vectors per work unit (one warp, 2 per lane)
#define NUNITS (NVEC / VPU)   // 2048

// smem: float2 s_e[DDIM][KP] (codebook, -2*E, pair-interleaved) + float2 s_esq[KP]
#define SME_BYTES   (DDIM * KP * 8)     // 131072
#define SESQ_BYTES  (KP * 8)            // 2048
#define SMEM_BYTES  (SME_BYTES + SESQ_BYTES)

__device__ double       g_loss = 0.0;
__device__ unsigned int g_unit = 0;
__device__ unsigned int g_done = 0;

__device__ __forceinline__ unsigned long long ffma2(unsigned long long a,
                                                    unsigned long long b,
                                                    unsigned long long c) {
    unsigned long long d;
    asm("fma.rn.f32x2 %0, %1, %2, %3;" : "=l"(d) : "l"(a), "l"(b), "l"(c));
    return d;
}

__device__ __forceinline__ unsigned long long pack2(float v) {
    unsigned long long r;
    asm("mov.b64 %0, {%1, %1};" : "=l"(r) : "r"(__float_as_uint(v)));
    return r;
}

__device__ __forceinline__ float lo32(unsigned long long a) {
    return __uint_as_float((unsigned)a);
}
__device__ __forceinline__ float hi32(unsigned long long a) {
    return __uint_as_float((unsigned)(a >> 32));
}

__global__ __launch_bounds__(TPB, 1)
void vq_kernel(const float* __restrict__ enc,
               const float* __restrict__ embed,
               float* __restrict__ out,
               int out_size) {
    extern __shared__ unsigned char sraw[];
    float2* s_e   = (float2*)sraw;                        // [DDIM][KP]
    float2* s_esq = (float2*)(sraw + SME_BYTES);          // [KP]

    const int tid  = threadIdx.x;
    const int lane = tid & 31;

    // ---- codebook -> smem: s_e[d*KP+p] = {-2*E[2p][d], -2*E[2p+1][d]}
    for (int idx = tid; idx < DDIM * KP; idx += TPB) {
        int d = idx >> 8;
        int p = idx & (KP - 1);
        float a = embed[(2 * p) * DDIM + d];
        float b = embed[(2 * p + 1) * DDIM + d];
        s_e[idx] = make_float2(-2.0f * a, -2.0f * b);
    }
    // ---- ||e||^2 pairs
    if (tid < KP) {
        float s0 = 0.f, s1 = 0.f;
        const float* e0 = embed + (2 * tid) * DDIM;
        const float* e1 = e0 + DDIM;
#pragma unroll
        for (int d = 0; d < DDIM; d++) { s0 += e0[d] * e0[d]; s1 += e1[d] * e1[d]; }
        s_esq[tid] = make_float2(s0, s1);
    }
    __syncthreads();

    float lsum = 0.f;

    // ---- persistent warp work-stealing over 64-vector units
    for (;;) {
        unsigned u;
        if (lane == 0) u = atomicAdd(&g_unit, 1u);
        u = __shfl_sync(0xffffffffu, u, 0);
        if (u >= NUNITS) break;

        const int v0 = (int)u * VPU + 2 * lane;   // this lane's two vectors
        const int v1 = v0 + 1;

        float x0[DDIM], x1[DDIM];
        {
            const float4* xp = (const float4*)(enc + (size_t)v0 * DDIM);
#pragma unroll
            for (int i = 0; i < DDIM / 4; i++) {
                float4 t = xp[i];
                x0[4*i+0] = t.x; x0[4*i+1] = t.y; x0[4*i+2] = t.z; x0[4*i+3] = t.w;
            }
            xp = (const float4*)(enc + (size_t)v1 * DDIM);
#pragma unroll
            for (int i = 0; i < DDIM / 4; i++) {
                float4 t = xp[i];
                x1[4*i+0] = t.x; x1[4*i+1] = t.y; x1[4*i+2] = t.z; x1[4*i+3] = t.w;
            }
        }

        float best0 = FLT_MAX, best1 = FLT_MAX;
        int   bi0 = 0, bi1 = 0;

#pragma unroll 1
        for (int p0 = 0; p0 < KP; p0 += 2) {     // 128 chunks, 4 codes (2 pairs) each
            const ulonglong2* erow = (const ulonglong2*)(s_e + p0);   // stride KP/2 ull2 per d
            ulonglong2 einit = *(const ulonglong2*)((const float2*)s_esq + p0);
            unsigned long long a00 = einit.x, a01 = einit.y;          // v0, pairs p0 / p0+1
            unsigned long long a10 = einit.x, a11 = einit.y;          // v1

            // software-pipelined d loop: prefetch next d's code pairs
            ulonglong2 t = erow[0];
#pragma unroll
            for (int d = 0; d < DDIM; d++) {
                ulonglong2 n;
                if (d < DDIM - 1) n = erow[(d + 1) * (KP / 2)];
                unsigned long long xa = pack2(x0[d]);
                unsigned long long xb = pack2(x1[d]);
                a00 = ffma2(xa, t.x, a00);
                a01 = ffma2(xa, t.y, a01);
                a10 = ffma2(xb, t.x, a10);
                a11 = ffma2(xb, t.y, a11);
                t = n;
            }

            // strict < in increasing code order == first-index argmin tie-break
            int k = 2 * p0;
            float f;
            f = lo32(a00); if (f < best0) { best0 = f; bi0 = k + 0; }
            f = hi32(a00); if (f < best0) { best0 = f; bi0 = k + 1; }
            f = lo32(a01); if (f < best0) { best0 = f; bi0 = k + 2; }
            f = hi32(a01); if (f < best0) { best0 = f; bi0 = k + 3; }

            f = lo32(a10); if (f < best1) { best1 = f; bi1 = k + 0; }
            f = hi32(a10); if (f < best1) { best1 = f; bi1 = k + 1; }
            f = lo32(a11); if (f < best1) { best1 = f; bi1 = k + 2; }
            f = hi32(a11); if (f < best1) { best1 = f; bi1 = k + 3; }
        }

        // ---- gather + write quantized, accumulate loss
        {
            const int pw = bi0 >> 1, hi = bi0 & 1;
            float4* op = (float4*)(out + (size_t)v0 * DDIM);
#pragma unroll
            for (int i = 0; i < DDIM / 4; i++) {
                float4 q; float e; float2 ee;
                ee = s_e[(4*i+0) * KP + pw]; e = -0.5f * (hi ? ee.y : ee.x); q.x = e;
                { float df = e - x0[4*i+0]; lsum += df * df; }
                ee = s_e[(4*i+1) * KP + pw]; e = -0.5f * (hi ? ee.y : ee.x); q.y = e;
                { float df = e - x0[4*i+1]; lsum += df * df; }
                ee = s_e[(4*i+2) * KP + pw]; e = -0.5f * (hi ? ee.y : ee.x); q.z = e;
                { float df = e - x0[4*i+2]; lsum += df * df; }
                ee = s_e[(4*i+3) * KP + pw]; e = -0.5f * (hi ? ee.y : ee.x); q.w = e;
                { float df = e - x0[4*i+3]; lsum += df * df; }
                op[i] = q;
            }
        }
        {
            const int pw = bi1 >> 1, hi = bi1 & 1;
            float4* op = (float4*)(out + (size_t)v1 * DDIM);
#pragma unroll
            for (int i = 0; i < DDIM / 4; i++) {
                float4 q; float e; float2 ee;
                ee = s_e[(4*i+0) * KP + pw]; e = -0.5f * (hi ? ee.y : ee.x); q.x = e;
                { float df = e - x1[4*i+0]; lsum += df * df; }
                ee = s_e[(4*i+1) * KP + pw]; e = -0.5f * (hi ? ee.y : ee.x); q.y = e;
                { float df = e - x1[4*i+1]; lsum += df * df; }
                ee = s_e[(4*i+2) * KP + pw]; e = -0.5f * (hi ? ee.y : ee.x); q.z = e;
                { float df = e - x1[4*i+2]; lsum += df * df; }
                ee = s_e[(4*i+3) * KP + pw]; e = -0.5f * (hi ? ee.y : ee.x); q.w = e;
                { float df = e - x1[4*i+3]; lsum += df * df; }
                op[i] = q;
            }
        }
        if (out_size >= NTOT + 1 + NVEC) {
            out[NTOT + 1 + v0] = (float)bi0;
            out[NTOT + 1 + v1] = (float)bi1;
        }
    }

    // ---- loss: warp reduce -> one atomicAdd per warp
    double ls = (double)lsum;
#pragma unroll
    for (int off = 16; off > 0; off >>= 1)
        ls += __shfl_down_sync(0xffffffffu, ls, off);
    if (lane == 0) atomicAdd(&g_loss, ls);

    // ---- last block finalizes: write loss scalar, reset all state
    __syncthreads();
    if (tid == 0) {
        __threadfence();
        unsigned done = atomicAdd(&g_done, 1u);
        if (done == GRID - 1) {
            unsigned long long bits =
                atomicExch((unsigned long long*)&g_loss, 0ull);  // read + reset
            double total = __longlong_as_double((long long)bits);
            if (out_size >= NTOT + 1)
                out[NTOT] = (float)(2.0 * total / (double)NTOT);
            atomicExch(&g_unit, 0u);
            atomicExch(&g_done, 0u);
        }
    }
}

extern "C" void kernel_launch(void* const* d_in, const int* in_sizes, int n_in,
                              void* d_out, int out_size) {
    const float* enc   = (const float*)d_in[0];
    const float* embed = (const float*)d_in[1];
    float* out = (float*)d_out;

    static bool attr_set = false;
    if (!attr_set) {
        cudaFuncSetAttribute(vq_kernel,
                             cudaFuncAttributeMaxDynamicSharedMemorySize,
                             SMEM_BYTES);
        attr_set = true;
    }

    vq_kernel<<<GRID, TPB, SMEM_BYTES>>>(enc, embed, out, out_size);
}

// round 5
// speedup vs baseline: 1.7349x; 1.7349x over previous
#include <cuda_runtime.h>
#include <cuda_bf16.h>
#include <cfloat>
#include <cstdint>

// Shapes: enc (32,64,64,64) fp32 -> 131072 vectors D=64; codebook (512,64) fp32.
#define DDIM    64
#define KCODE   512
#define NTOT    8388608
#define NVEC    131072
#define TPB     256
#define GRID    148
#define MTILE   128
#define NTILES  (NVEC / MTILE)   // 1024

// SMEM: B fragments (3 terms x 512 codes x 128B) + esq + bi + tile
#define B_OFF     0
#define B_TERM    65536                  // 512 * 128
#define ESQ_OFF   (3 * B_TERM)           // 196608
#define BI_OFF    (ESQ_OFF + 2048)       // 198656
#define TILE_OFF  (BI_OFF + 512)         // 199168
#define SMEM_TOTAL (TILE_OFF + 16)       // 199184

__device__ double       g_loss = 0.0;
__device__ unsigned int g_unit = 0;
__device__ unsigned int g_done = 0;

__device__ __forceinline__ void mma_bf16(float c[4], const unsigned a[4],
                                         unsigned b0, unsigned b1) {
    asm volatile(
        "mma.sync.aligned.m16n8k16.row.col.f32.bf16.bf16.f32 "
        "{%0,%1,%2,%3}, {%4,%5,%6,%7}, {%8,%9}, {%0,%1,%2,%3};"
        : "+f"(c[0]), "+f"(c[1]), "+f"(c[2]), "+f"(c[3])
        : "r"(a[0]), "r"(a[1]), "r"(a[2]), "r"(a[3]), "r"(b0), "r"(b1));
}

// exact fp32 -> 3x bf16 split (h+m+l == f up to ~2^-27 rel)
__device__ __forceinline__ void split3(float f, unsigned short& h,
                                       unsigned short& m, unsigned short& l) {
    __nv_bfloat16 bh = __float2bfloat16_rn(f);
    float r1 = f - __bfloat162float(bh);
    __nv_bfloat16 bm = __float2bfloat16_rn(r1);
    __nv_bfloat16 bl = __float2bfloat16_rn(r1 - __bfloat162float(bm));
    h = __bfloat16_as_ushort(bh);
    m = __bfloat16_as_ushort(bm);
    l = __bfloat16_as_ushort(bl);
}
__device__ __forceinline__ unsigned pk(unsigned short a, unsigned short b) {
    return (unsigned)a | ((unsigned)b << 16);
}

__global__ __launch_bounds__(TPB, 1)
void vq_mma_kernel(const float* __restrict__ enc,
                   const float* __restrict__ embed,
                   float* __restrict__ out,
                   int out_size) {
    extern __shared__ unsigned char sraw[];
    float* s_esq = (float*)(sraw + ESQ_OFF);
    int*   s_bi  = (int*)(sraw + BI_OFF);
    volatile unsigned* s_tile = (volatile unsigned*)(sraw + TILE_OFF);

    const int tid  = threadIdx.x;
    const int wid  = tid >> 5;
    const int lane = tid & 31;
    const int rq   = lane >> 2;   // row-in-group 0..7
    const int q    = lane & 3;    // col-group 0..3

    // ---- one-time per CTA: codebook -> b-fragment-order SMEM (-2*e, 3-way split) + esq
    for (int n = tid; n < KCODE; n += TPB) {
        const float4* g4 = (const float4*)(embed + (size_t)n * DDIM);
        float esq = 0.f;
        const unsigned rot = (unsigned)(n & 3);
#pragma unroll
        for (int ks = 0; ks < 4; ks++) {
            float f[16];
#pragma unroll
            for (int i = 0; i < 4; i++) {
                float4 t = g4[ks * 4 + i];
                f[4*i+0] = t.x; f[4*i+1] = t.y; f[4*i+2] = t.z; f[4*i+3] = t.w;
            }
            unsigned short h[16], m[16], l[16];
#pragma unroll
            for (int i = 0; i < 16; i++) {
                esq += f[i] * f[i];
                split3(-2.0f * f[i], h[i], m[i], l[i]);
            }
            unsigned base = (unsigned)n * 128u + (((unsigned)ks + rot) & 3u) * 32u;
#pragma unroll
            for (int qq = 0; qq < 4; qq++) {
                int k0 = 2 * qq;
                unsigned a = base + (unsigned)qq * 8u;
                *(uint2*)(sraw + 0 * B_TERM + a) =
                    make_uint2(pk(h[k0], h[k0+1]), pk(h[k0+8], h[k0+9]));
                *(uint2*)(sraw + 1 * B_TERM + a) =
                    make_uint2(pk(m[k0], m[k0+1]), pk(m[k0+8], m[k0+9]));
                *(uint2*)(sraw + 2 * B_TERM + a) =
                    make_uint2(pk(l[k0], l[k0+1]), pk(l[k0+8], l[k0+9]));
            }
        }
        s_esq[n] = esq;
    }
    __syncthreads();

    float lsum = 0.f;

    for (;;) {
        if (tid == 0) *s_tile = atomicAdd(&g_unit, 1u);
        __syncthreads();
        const unsigned tile = *s_tile;
        if (tile >= NTILES) break;

        // ---- A fragments (registers): rows r0 = tile*128 + wid*16 + rq, r1 = r0+8
        unsigned aF[3][4][4];   // [term][kstep][reg]
        float sq0 = 0.f, sq1 = 0.f;
        {
            const size_t r0 = (size_t)tile * MTILE + wid * 16 + rq;
            const float* p0 = enc + r0 * DDIM;
            const float* p1 = p0 + 8 * DDIM;
#pragma unroll
            for (int ks = 0; ks < 4; ks++) {
                const int c0 = 16 * ks + 2 * q;
                float2 x0a = *(const float2*)(p0 + c0);
                float2 x0b = *(const float2*)(p0 + c0 + 8);
                float2 x1a = *(const float2*)(p1 + c0);
                float2 x1b = *(const float2*)(p1 + c0 + 8);
                sq0 += x0a.x*x0a.x + x0a.y*x0a.y + x0b.x*x0b.x + x0b.y*x0b.y;
                sq1 += x1a.x*x1a.x + x1a.y*x1a.y + x1b.x*x1b.x + x1b.y*x1b.y;
                unsigned short h0,m0,l0, h1,m1,l1;
                // reg0: (r0, c0 pair)
                split3(x0a.x, h0, m0, l0); split3(x0a.y, h1, m1, l1);
                aF[0][ks][0] = pk(h0,h1); aF[1][ks][0] = pk(m0,m1); aF[2][ks][0] = pk(l0,l1);
                // reg1: (r1, c0 pair)
                split3(x1a.x, h0, m0, l0); split3(x1a.y, h1, m1, l1);
                aF[0][ks][1] = pk(h0,h1); aF[1][ks][1] = pk(m0,m1); aF[2][ks][1] = pk(l0,l1);
                // reg2: (r0, c0+8 pair)
                split3(x0b.x, h0, m0, l0); split3(x0b.y, h1, m1, l1);
                aF[0][ks][2] = pk(h0,h1); aF[1][ks][2] = pk(m0,m1); aF[2][ks][2] = pk(l0,l1);
                // reg3: (r1, c0+8 pair)
                split3(x1b.x, h0, m0, l0); split3(x1b.y, h1, m1, l1);
                aF[0][ks][3] = pk(h0,h1); aF[1][ks][3] = pk(m0,m1); aF[2][ks][3] = pk(l0,l1);
            }
        }
        // full row ||x||^2 across the 4-lane group
        sq0 += __shfl_xor_sync(0xffffffffu, sq0, 1);
        sq0 += __shfl_xor_sync(0xffffffffu, sq0, 2);
        sq1 += __shfl_xor_sync(0xffffffffu, sq1, 1);
        sq1 += __shfl_xor_sync(0xffffffffu, sq1, 2);

        float best0 = FLT_MAX, best1 = FLT_MAX;
        int   bi0 = 0, bi1 = 0;

#pragma unroll 1
        for (int chunk = 0; chunk < 8; chunk++) {
            float c[8][4];
            const int nbase = chunk * 64 + rq;          // b-frag n for nf=0
#pragma unroll
            for (int nf = 0; nf < 8; nf++) {            // init C with ||e||^2
                int n0 = chunk * 64 + nf * 8 + 2 * q;
                float2 e2 = *(const float2*)(s_esq + n0);
                c[nf][0] = e2.x; c[nf][1] = e2.y;
                c[nf][2] = e2.x; c[nf][3] = e2.y;
            }
            const unsigned rowb = (unsigned)nbase * 128u + (unsigned)q * 8u;
            static const int at[6] = {0, 0, 1, 1, 0, 2};
            static const int bt[6] = {0, 1, 0, 1, 2, 0};
#pragma unroll
            for (int t = 0; t < 6; t++) {
#pragma unroll
                for (int ks = 0; ks < 4; ks++) {
                    const unsigned rot = (((unsigned)ks + (unsigned)rq) & 3u) * 32u;
                    const unsigned char* bp =
                        sraw + bt[t] * B_TERM + rowb + rot;
#pragma unroll
                    for (int nf = 0; nf < 8; nf++) {
                        uint2 b = *(const uint2*)(bp + nf * 1024);
                        mma_bf16(c[nf], aF[at[t]][ks], b.x, b.y);
                    }
                }
            }
            // argmin (strict <, ascending n => first-index tie-break)
#pragma unroll
            for (int nf = 0; nf < 8; nf++) {
                int n0 = chunk * 64 + nf * 8 + 2 * q;
                if (c[nf][0] < best0) { best0 = c[nf][0]; bi0 = n0; }
                if (c[nf][1] < best0) { best0 = c[nf][1]; bi0 = n0 + 1; }
                if (c[nf][2] < best1) { best1 = c[nf][2]; bi1 = n0; }
                if (c[nf][3] < best1) { best1 = c[nf][3]; bi1 = n0 + 1; }
            }
        }

        // combine across the 4 lanes sharing rows (tie -> smaller index)
#pragma unroll
        for (int off = 1; off <= 2; off <<= 1) {
            float ob = __shfl_xor_sync(0xffffffffu, best0, off);
            int   oi = __shfl_xor_sync(0xffffffffu, bi0, off);
            if (ob < best0 || (ob == best0 && oi < bi0)) { best0 = ob; bi0 = oi; }
            ob = __shfl_xor_sync(0xffffffffu, best1, off);
            oi = __shfl_xor_sync(0xffffffffu, bi1, off);
            if (ob < best1 || (ob == best1 && oi < bi1)) { best1 = ob; bi1 = oi; }
        }

        if (q == 0) {
            const int r = wid * 16 + rq;
            s_bi[r]     = bi0;
            s_bi[r + 8] = bi1;
            lsum += sq0 + best0 + sq1 + best1;    // ||x-e||^2 = ||x||^2 + (esq - 2xe)
            const int v = (int)tile * MTILE + r;
            if (out_size >= NTOT + 1 + NVEC) {
                out[NTOT + 1 + v]     = (float)bi0;
                out[NTOT + 1 + v + 8] = (float)bi1;
            }
        }
        __syncthreads();

        // cooperative quantized gather/write: 2 threads per row
        {
            const int r    = tid >> 1;
            const int half = tid & 1;
            const int b    = s_bi[r];
            const float4* ep = (const float4*)(embed + (size_t)b * DDIM + half * 32);
            float4* op = (float4*)(out + ((size_t)tile * MTILE + r) * DDIM + half * 32);
#pragma unroll
            for (int i = 0; i < 8; i++) op[i] = ep[i];
        }
        __syncthreads();
    }

    // ---- loss reduce -> global
    double ls = (double)lsum;
#pragma unroll
    for (int off = 16; off > 0; off >>= 1)
        ls += __shfl_down_sync(0xffffffffu, ls, off);
    if (lane == 0) atomicAdd(&g_loss, ls);

    __syncthreads();
    if (tid == 0) {
        __threadfence();
        unsigned done = atomicAdd(&g_done, 1u);
        if (done == GRID - 1) {
            unsigned long long bits =
                atomicExch((unsigned long long*)&g_loss, 0ull);
            double total = __longlong_as_double((long long)bits);
            if (out_size >= NTOT + 1)
                out[NTOT] = (float)(2.0 * total / (double)NTOT);
            atomicExch(&g_unit, 0u);
            atomicExch(&g_done, 0u);
        }
    }
}

extern "C" void kernel_launch(void* const* d_in, const int* in_sizes, int n_in,
                              void* d_out, int out_size) {
    const float* enc   = (const float*)d_in[0];
    const float* embed = (const float*)d_in[1];
    float* out = (float*)d_out;

    static bool attr_set = false;
    if (!attr_set) {
        cudaFuncSetAttribute(vq_mma_kernel,
                             cudaFuncAttributeMaxDynamicSharedMemorySize,
                             SMEM_TOTAL);
        attr_set = true;
    }

    vq_mma_kernel<<<GRID, TPB, SMEM_TOTAL>>>(enc, embed, out, out_size);
}

// round 6
// speedup vs baseline: 1.9301x; 1.1125x over previous
#include <cuda_runtime.h>
#include <cuda_bf16.h>
#include <cfloat>
#include <cstdint>

// Shapes: enc (32,64,64,64) fp32 -> 131072 vectors D=64; codebook (512,64) fp32.
#define DDIM    64
#define KCODE   512
#define NTOT    8388608
#define NVEC    131072
#define TPB     384
#define GRID    148
#define NROWS   16                 // rows per warp work unit
#define NUNITS  (NVEC / NROWS)     // 8192

// SMEM: B fragments (3 terms x 512 codes x 128B) + esq
#define B_TERM    65536                  // 512 * 128
#define ESQ_OFF   (3 * B_TERM)           // 196608
#define SMEM_TOTAL (ESQ_OFF + 2048)      // 198656

__device__ double       g_loss = 0.0;
__device__ unsigned int g_unit = 0;
__device__ unsigned int g_done = 0;

__device__ __forceinline__ void mma_bf16(float c[4], const unsigned a[4],
                                         unsigned b0, unsigned b1) {
    asm volatile(
        "mma.sync.aligned.m16n8k16.row.col.f32.bf16.bf16.f32 "
        "{%0,%1,%2,%3}, {%4,%5,%6,%7}, {%8,%9}, {%0,%1,%2,%3};"
        : "+f"(c[0]), "+f"(c[1]), "+f"(c[2]), "+f"(c[3])
        : "r"(a[0]), "r"(a[1]), "r"(a[2]), "r"(a[3]), "r"(b0), "r"(b1));
}

// exact fp32 -> 3x bf16 split (h+m+l == f up to ~2^-27 rel)
__device__ __forceinline__ void split3(float f, unsigned short& h,
                                       unsigned short& m, unsigned short& l) {
    __nv_bfloat16 bh = __float2bfloat16_rn(f);
    float r1 = f - __bfloat162float(bh);
    __nv_bfloat16 bm = __float2bfloat16_rn(r1);
    __nv_bfloat16 bl = __float2bfloat16_rn(r1 - __bfloat162float(bm));
    h = __bfloat16_as_ushort(bh);
    m = __bfloat16_as_ushort(bm);
    l = __bfloat16_as_ushort(bl);
}
__device__ __forceinline__ unsigned pk(unsigned short a, unsigned short b) {
    return (unsigned)a | ((unsigned)b << 16);
}

__global__ __launch_bounds__(TPB, 1)
void vq_mma_kernel(const float* __restrict__ enc,
                   const float* __restrict__ embed,
                   float* __restrict__ out,
                   int out_size) {
    extern __shared__ unsigned char sraw[];
    float* s_esq = (float*)(sraw + ESQ_OFF);

    const int tid  = threadIdx.x;
    const int lane = tid & 31;
    const int rq   = lane >> 2;   // row-in-group 0..7
    const int q    = lane & 3;    // col-group 0..3

    // ---- one-time per CTA: codebook -> b-fragment-order SMEM (-2*e, 3-way split) + esq
    for (int n = tid; n < KCODE; n += TPB) {
        const float4* g4 = (const float4*)(embed + (size_t)n * DDIM);
        float esq = 0.f;
        const unsigned rot = (unsigned)(n & 3);
#pragma unroll
        for (int ks = 0; ks < 4; ks++) {
            float f[16];
#pragma unroll
            for (int i = 0; i < 4; i++) {
                float4 t = g4[ks * 4 + i];
                f[4*i+0] = t.x; f[4*i+1] = t.y; f[4*i+2] = t.z; f[4*i+3] = t.w;
            }
            unsigned short h[16], m[16], l[16];
#pragma unroll
            for (int i = 0; i < 16; i++) {
                esq += f[i] * f[i];
                split3(-2.0f * f[i], h[i], m[i], l[i]);
            }
            unsigned base = (unsigned)n * 128u + (((unsigned)ks + rot) & 3u) * 32u;
#pragma unroll
            for (int qq = 0; qq < 4; qq++) {
                int k0 = 2 * qq;
                unsigned a = base + (unsigned)qq * 8u;
                *(uint2*)(sraw + 0 * B_TERM + a) =
                    make_uint2(pk(h[k0], h[k0+1]), pk(h[k0+8], h[k0+9]));
                *(uint2*)(sraw + 1 * B_TERM + a) =
                    make_uint2(pk(m[k0], m[k0+1]), pk(m[k0+8], m[k0+9]));
                *(uint2*)(sraw + 2 * B_TERM + a) =
                    make_uint2(pk(l[k0], l[k0+1]), pk(l[k0+8], l[k0+9]));
            }
        }
        s_esq[n] = esq;
    }
    __syncthreads();

    float lsum = 0.f;

    // ---- per-warp persistent work-stealing over 16-row units
    for (;;) {
        unsigned u;
        if (lane == 0) u = atomicAdd(&g_unit, 1u);
        u = __shfl_sync(0xffffffffu, u, 0);
        if (u >= NUNITS) break;

        // ---- A fragments (registers): rows r0 = u*16 + rq, r1 = r0 + 8
        unsigned aF[3][4][4];   // [term][kstep][reg]
        float sq0 = 0.f, sq1 = 0.f;
        {
            const float* p0 = enc + ((size_t)u * NROWS + rq) * DDIM;
            const float* p1 = p0 + 8 * DDIM;
#pragma unroll
            for (int ks = 0; ks < 4; ks++) {
                const int c0 = 16 * ks + 2 * q;
                float2 x0a = *(const float2*)(p0 + c0);
                float2 x0b = *(const float2*)(p0 + c0 + 8);
                float2 x1a = *(const float2*)(p1 + c0);
                float2 x1b = *(const float2*)(p1 + c0 + 8);
                sq0 += x0a.x*x0a.x + x0a.y*x0a.y + x0b.x*x0b.x + x0b.y*x0b.y;
                sq1 += x1a.x*x1a.x + x1a.y*x1a.y + x1b.x*x1b.x + x1b.y*x1b.y;
                unsigned short h0,m0,l0, h1,m1,l1;
                split3(x0a.x, h0, m0, l0); split3(x0a.y, h1, m1, l1);
                aF[0][ks][0] = pk(h0,h1); aF[1][ks][0] = pk(m0,m1); aF[2][ks][0] = pk(l0,l1);
                split3(x1a.x, h0, m0, l0); split3(x1a.y, h1, m1, l1);
                aF[0][ks][1] = pk(h0,h1); aF[1][ks][1] = pk(m0,m1); aF[2][ks][1] = pk(l0,l1);
                split3(x0b.x, h0, m0, l0); split3(x0b.y, h1, m1, l1);
                aF[0][ks][2] = pk(h0,h1); aF[1][ks][2] = pk(m0,m1); aF[2][ks][2] = pk(l0,l1);
                split3(x1b.x, h0, m0, l0); split3(x1b.y, h1, m1, l1);
                aF[0][ks][3] = pk(h0,h1); aF[1][ks][3] = pk(m0,m1); aF[2][ks][3] = pk(l0,l1);
            }
        }
        // full row ||x||^2 across the 4-lane group
        sq0 += __shfl_xor_sync(0xffffffffu, sq0, 1);
        sq0 += __shfl_xor_sync(0xffffffffu, sq0, 2);
        sq1 += __shfl_xor_sync(0xffffffffu, sq1, 1);
        sq1 += __shfl_xor_sync(0xffffffffu, sq1, 2);

        float best0 = FLT_MAX, best1 = FLT_MAX;
        int   bi0 = 0, bi1 = 0;

#pragma unroll 1
        for (int chunk = 0; chunk < 8; chunk++) {
            float c[8][4];
#pragma unroll
            for (int nf = 0; nf < 8; nf++) {            // init C with ||e||^2
                int n0 = chunk * 64 + nf * 8 + 2 * q;
                float2 e2 = *(const float2*)(s_esq + n0);
                c[nf][0] = e2.x; c[nf][1] = e2.y;
                c[nf][2] = e2.x; c[nf][3] = e2.y;
            }
            const unsigned rowb = ((unsigned)(chunk * 64 + rq)) * 128u + (unsigned)q * 8u;
#pragma unroll
            for (int ks = 0; ks < 4; ks++) {
                const unsigned rot = (((unsigned)ks + (unsigned)rq) & 3u) * 32u;
                const unsigned char* bp = sraw + rowb + rot;
#pragma unroll
                for (int nf = 0; nf < 8; nf++) {
                    const unsigned char* p = bp + nf * 1024;
                    uint2 bh = *(const uint2*)(p);
                    uint2 bm = *(const uint2*)(p + B_TERM);
                    uint2 bl = *(const uint2*)(p + 2 * B_TERM);
                    mma_bf16(c[nf], aF[0][ks], bh.x, bh.y);   // hh
                    mma_bf16(c[nf], aF[0][ks], bm.x, bm.y);   // hm
                    mma_bf16(c[nf], aF[1][ks], bh.x, bh.y);   // mh
                    mma_bf16(c[nf], aF[1][ks], bm.x, bm.y);   // mm
                    mma_bf16(c[nf], aF[0][ks], bl.x, bl.y);   // hl
                    mma_bf16(c[nf], aF[2][ks], bh.x, bh.y);   // lh
                }
            }
            // argmin (strict <, ascending n => first-index tie-break)
#pragma unroll
            for (int nf = 0; nf < 8; nf++) {
                int n0 = chunk * 64 + nf * 8 + 2 * q;
                if (c[nf][0] < best0) { best0 = c[nf][0]; bi0 = n0; }
                if (c[nf][1] < best0) { best0 = c[nf][1]; bi0 = n0 + 1; }
                if (c[nf][2] < best1) { best1 = c[nf][2]; bi1 = n0; }
                if (c[nf][3] < best1) { best1 = c[nf][3]; bi1 = n0 + 1; }
            }
        }

        // combine across the 4 lanes sharing rows (tie -> smaller index)
#pragma unroll
        for (int off = 1; off <= 2; off <<= 1) {
            float ob = __shfl_xor_sync(0xffffffffu, best0, off);
            int   oi = __shfl_xor_sync(0xffffffffu, bi0, off);
            if (ob < best0 || (ob == best0 && oi < bi0)) { best0 = ob; bi0 = oi; }
            ob = __shfl_xor_sync(0xffffffffu, best1, off);
            oi = __shfl_xor_sync(0xffffffffu, bi1, off);
            if (ob < best1 || (ob == best1 && oi < bi1)) { best1 = ob; bi1 = oi; }
        }

        if (q == 0) {
            lsum += sq0 + best0 + sq1 + best1;    // ||x-e||^2 = ||x||^2 + (esq - 2xe)
            const int v = (int)u * NROWS + rq;
            if (out_size >= NTOT + 1 + NVEC) {
                out[NTOT + 1 + v]     = (float)bi0;
                out[NTOT + 1 + v + 8] = (float)bi1;
            }
        }

        // quantized gather/write: lane handles row (lane&15), half (lane>>4)
        {
            const int r    = lane & 15;
            const int half = lane >> 4;
            int src  = 4 * (r & 7);
            int from0 = __shfl_sync(0xffffffffu, bi0, src);
            int from1 = __shfl_sync(0xffffffffu, bi1, src);
            const int b = (r < 8) ? from0 : from1;
            const float4* ep = (const float4*)(embed + (size_t)b * DDIM + half * 32);
            float4* op = (float4*)(out + ((size_t)u * NROWS + r) * DDIM + half * 32);
#pragma unroll
            for (int i = 0; i < 8; i++) op[i] = ep[i];
        }
    }

    // ---- loss reduce -> global
    double ls = (double)lsum;
#pragma unroll
    for (int off = 16; off > 0; off >>= 1)
        ls += __shfl_down_sync(0xffffffffu, ls, off);
    if (lane == 0) atomicAdd(&g_loss, ls);

    __syncthreads();
    if (tid == 0) {
        __threadfence();
        unsigned done = atomicAdd(&g_done, 1u);
        if (done == GRID - 1) {
            unsigned long long bits =
                atomicExch((unsigned long long*)&g_loss, 0ull);
            double total = __longlong_as_double((long long)bits);
            if (out_size >= NTOT + 1)
                out[NTOT] = (float)(2.0 * total / (double)NTOT);
            atomicExch(&g_unit, 0u);
            atomicExch(&g_done, 0u);
        }
    }
}

extern "C" void kernel_launch(void* const* d_in, const int* in_sizes, int n_in,
                              void* d_out, int out_size) {
    const float* enc   = (const float*)d_in[0];
    const float* embed = (const float*)d_in[1];
    float* out = (float*)d_out;

    static bool attr_set = false;
    if (!attr_set) {
        cudaFuncSetAttribute(vq_mma_kernel,
                             cudaFuncAttributeMaxDynamicSharedMemorySize,
                             SMEM_TOTAL);
        attr_set = true;
    }

    vq_mma_kernel<<<GRID, TPB, SMEM_TOTAL>>>(enc, embed, out, out_size);
}

// round 11
// speedup vs baseline: 2.0044x; 1.0385x over previous
#include <cuda_runtime.h>
#include <cuda_fp16.h>
#include <cfloat>
#include <cstdint>

// Shapes: enc (32,64,64,64) fp32 -> 131072 vectors D=64; codebook (512,64) fp32.
#define DDIM    64
#define KCODE   512
#define NTOT    8388608
#define NVEC    131072
#define TPB     512
#define GRID    148
#define NROWS   16                 // rows per warp work unit
#define NUNITS  (NVEC / NROWS)     // 8192
#define BAND    2e-4f              // recheck band (>> dropped-term error bound)

// SMEM: B fragments (2 terms x 512 codes x 128B) + esq
#define B_TERM    65536                  // 512 * 128
#define ESQ_OFF   (2 * B_TERM)           // 131072
#define SMEM_TOTAL (ESQ_OFF + 2048)      // 133120

__device__ double       g_loss = 0.0;
__device__ unsigned int g_unit = 0;
__device__ unsigned int g_done = 0;

__device__ __forceinline__ void mma_f16(float c[4], const unsigned a[4],
                                        unsigned b0, unsigned b1) {
    asm volatile(
        "mma.sync.aligned.m16n8k16.row.col.f32.f16.f16.f32 "
        "{%0,%1,%2,%3}, {%4,%5,%6,%7}, {%8,%9}, {%0,%1,%2,%3};"
        : "+f"(c[0]), "+f"(c[1]), "+f"(c[2]), "+f"(c[3])
        : "r"(a[0]), "r"(a[1]), "r"(a[2]), "r"(a[3]), "r"(b0), "r"(b1));
}

// fp32 -> 2x fp16 split: h+m == f up to ~2^-24 rel (residual handled by recheck)
__device__ __forceinline__ void split2(float f, unsigned short& h, unsigned short& m) {
    __half hh = __float2half_rn(f);
    float r = f - __half2float(hh);
    __half hm = __float2half_rn(r);
    h = __half_as_ushort(hh);
    m = __half_as_ushort(hm);
}
__device__ __forceinline__ unsigned pk(unsigned short a, unsigned short b) {
    return (unsigned)a | ((unsigned)b << 16);
}

// top-2 tracker update (strict <; ascending scan order => first-index tie-break on b1)
__device__ __forceinline__ void upd2(float d, int n, float& b1, int& i1,
                                     float& b2, int& i2) {
    if (d < b1) { b2 = b1; i2 = i1; b1 = d; i1 = n; }
    else if (d < b2) { b2 = d; i2 = n; }
}

__global__ __launch_bounds__(TPB, 1)
void vq_mma_kernel(const float* __restrict__ enc,
                   const float* __restrict__ embed,
                   float* __restrict__ out,
                   int out_size) {
    extern __shared__ unsigned char sraw[];
    float* s_esq = (float*)(sraw + ESQ_OFF);

    const int tid  = threadIdx.x;
    const int lane = tid & 31;
    const int rq   = lane >> 2;   // row-in-group 0..7
    const int q    = lane & 3;    // col-group 0..3

    // ---- one-time per CTA: codebook -> b-fragment-order SMEM (-2*e, 2-way fp16 split) + esq
    for (int n = tid; n < KCODE; n += TPB) {
        const float4* g4 = (const float4*)(embed + (size_t)n * DDIM);
        float esq = 0.f;
        const unsigned rot = (unsigned)(n & 3);
#pragma unroll
        for (int ks = 0; ks < 4; ks++) {
            float f[16];
#pragma unroll
            for (int i = 0; i < 4; i++) {
                float4 t = g4[ks * 4 + i];
                f[4*i+0] = t.x; f[4*i+1] = t.y; f[4*i+2] = t.z; f[4*i+3] = t.w;
            }
            unsigned short h[16], m[16];
#pragma unroll
            for (int i = 0; i < 16; i++) {
                esq += f[i] * f[i];
                split2(-2.0f * f[i], h[i], m[i]);
            }
            unsigned base = (unsigned)n * 128u + (((unsigned)ks + rot) & 3u) * 32u;
#pragma unroll
            for (int qq = 0; qq < 4; qq++) {
                int k0 = 2 * qq;
                unsigned a = base + (unsigned)qq * 8u;
                *(uint2*)(sraw + 0 * B_TERM + a) =
                    make_uint2(pk(h[k0], h[k0+1]), pk(h[k0+8], h[k0+9]));
                *(uint2*)(sraw + 1 * B_TERM + a) =
                    make_uint2(pk(m[k0], m[k0+1]), pk(m[k0+8], m[k0+9]));
            }
        }
        s_esq[n] = esq;
    }
    __syncthreads();

    float lsum = 0.f;

    // ---- per-warp persistent work-stealing over 16-row units
    for (;;) {
        unsigned u;
        if (lane == 0) u = atomicAdd(&g_unit, 1u);
        u = __shfl_sync(0xffffffffu, u, 0);
        if (u >= NUNITS) break;

        // ---- A fragments (registers): rows r0 = u*16 + rq, r1 = r0 + 8
        unsigned aF[2][4][4];   // [term][kstep][reg]
        float sq0 = 0.f, sq1 = 0.f;
        {
            const float* p0 = enc + ((size_t)u * NROWS + rq) * DDIM;
            const float* p1 = p0 + 8 * DDIM;
#pragma unroll
            for (int ks = 0; ks < 4; ks++) {
                const int c0 = 16 * ks + 2 * q;
                float2 x0a = *(const float2*)(p0 + c0);
                float2 x0b = *(const float2*)(p0 + c0 + 8);
                float2 x1a = *(const float2*)(p1 + c0);
                float2 x1b = *(const float2*)(p1 + c0 + 8);
                sq0 += x0a.x*x0a.x + x0a.y*x0a.y + x0b.x*x0b.x + x0b.y*x0b.y;
                sq1 += x1a.x*x1a.x + x1a.y*x1a.y + x1b.x*x1b.x + x1b.y*x1b.y;
                unsigned short h0,m0, h1,m1;
                split2(x0a.x, h0, m0); split2(x0a.y, h1, m1);
                aF[0][ks][0] = pk(h0,h1); aF[1][ks][0] = pk(m0,m1);
                split2(x1a.x, h0, m0); split2(x1a.y, h1, m1);
                aF[0][ks][1] = pk(h0,h1); aF[1][ks][1] = pk(m0,m1);
                split2(x0b.x, h0, m0); split2(x0b.y, h1, m1);
                aF[0][ks][2] = pk(h0,h1); aF[1][ks][2] = pk(m0,m1);
                split2(x1b.x, h0, m0); split2(x1b.y, h1, m1);
                aF[0][ks][3] = pk(h0,h1); aF[1][ks][3] = pk(m0,m1);
            }
        }
        // full row ||x||^2 across the 4-lane group
        sq0 += __shfl_xor_sync(0xffffffffu, sq0, 1);
        sq0 += __shfl_xor_sync(0xffffffffu, sq0, 2);
        sq1 += __shfl_xor_sync(0xffffffffu, sq1, 1);
        sq1 += __shfl_xor_sync(0xffffffffu, sq1, 2);

        float b1_0 = FLT_MAX, b2_0 = FLT_MAX, b1_1 = FLT_MAX, b2_1 = FLT_MAX;
        int   i1_0 = 0, i2_0 = 0, i1_1 = 0, i2_1 = 0;

#pragma unroll 1
        for (int chunk = 0; chunk < 8; chunk++) {
            float c[8][4];
#pragma unroll
            for (int nf = 0; nf < 8; nf++) {            // init C with ||e||^2
                int n0 = chunk * 64 + nf * 8 + 2 * q;
                float2 e2 = *(const float2*)(s_esq + n0);
                c[nf][0] = e2.x; c[nf][1] = e2.y;
                c[nf][2] = e2.x; c[nf][3] = e2.y;
            }
            const unsigned rowb = ((unsigned)(chunk * 64 + rq)) * 128u + (unsigned)q * 8u;
#pragma unroll
            for (int ks = 0; ks < 4; ks++) {
                const unsigned rot = (((unsigned)ks + (unsigned)rq) & 3u) * 32u;
                const unsigned char* bp = sraw + rowb + rot;
#pragma unroll
                for (int nf = 0; nf < 8; nf++) {
                    const unsigned char* p = bp + nf * 1024;
                    uint2 bh = *(const uint2*)(p);
                    uint2 bm = *(const uint2*)(p + B_TERM);
                    mma_f16(c[nf], aF[0][ks], bh.x, bh.y);   // hh
                    mma_f16(c[nf], aF[0][ks], bm.x, bm.y);   // hm
                    mma_f16(c[nf], aF[1][ks], bh.x, bh.y);   // mh
                    mma_f16(c[nf], aF[1][ks], bm.x, bm.y);   // mm
                }
            }
#pragma unroll
            for (int nf = 0; nf < 8; nf++) {
                int n0 = chunk * 64 + nf * 8 + 2 * q;
                upd2(c[nf][0], n0,     b1_0, i1_0, b2_0, i2_0);
                upd2(c[nf][1], n0 + 1, b1_0, i1_0, b2_0, i2_0);
                upd2(c[nf][2], n0,     b1_1, i1_1, b2_1, i2_1);
                upd2(c[nf][3], n0 + 1, b1_1, i1_1, b2_1, i2_1);
            }
        }

        // ---- merge top-2 across the 4 lanes sharing rows
#pragma unroll
        for (int off = 1; off <= 2; off <<= 1) {
            float ob1, ob2; int oi1, oi2;
            ob1 = __shfl_xor_sync(0xffffffffu, b1_0, off);
            oi1 = __shfl_xor_sync(0xffffffffu, i1_0, off);
            ob2 = __shfl_xor_sync(0xffffffffu, b2_0, off);
            oi2 = __shfl_xor_sync(0xffffffffu, i2_0, off);
            if (ob1 < b1_0 || (ob1 == b1_0 && oi1 < i1_0)) {
                if (b1_0 < ob2 || (b1_0 == ob2 && i1_0 < oi2)) { b2_0 = b1_0; i2_0 = i1_0; }
                else { b2_0 = ob2; i2_0 = oi2; }
                b1_0 = ob1; i1_0 = oi1;
            } else if (ob1 < b2_0 || (ob1 == b2_0 && oi1 < i2_0)) {
                b2_0 = ob1; i2_0 = oi1;
            }
            ob1 = __shfl_xor_sync(0xffffffffu, b1_1, off);
            oi1 = __shfl_xor_sync(0xffffffffu, i1_1, off);
            ob2 = __shfl_xor_sync(0xffffffffu, b2_1, off);
            oi2 = __shfl_xor_sync(0xffffffffu, i2_1, off);
            if (ob1 < b1_1 || (ob1 == b1_1 && oi1 < i1_1)) {
                if (b1_1 < ob2 || (b1_1 == ob2 && i1_1 < oi2)) { b2_1 = b1_1; i2_1 = i1_1; }
                else { b2_1 = ob2; i2_1 = oi2; }
                b1_1 = ob1; i1_1 = oi1;
            } else if (ob1 < b2_1 || (ob1 == b2_1 && oi1 < i2_1)) {
                b2_1 = ob1; i2_1 = oi1;
            }
        }

        if (q == 0) {
            // ---- rare exact recheck when gap inside error band (double precision)
            const int row0 = (int)u * NROWS + rq;
#pragma unroll
            for (int s = 0; s < 2; s++) {
                float b1 = s ? b1_1 : b1_0, b2 = s ? b2_1 : b2_0;
                int   i1 = s ? i1_1 : i1_0, i2 = s ? i2_1 : i2_0;
                const int row = row0 + 8 * s;
                float contrib = (s ? sq1 : sq0) + b1;
                if (b2 - b1 < BAND) {
                    const float* xp  = enc + (size_t)row * DDIM;
                    const float* e1p = embed + (size_t)i1 * DDIM;
                    const float* e2p = embed + (size_t)i2 * DDIM;
                    double d1 = 0.0, d2 = 0.0;
#pragma unroll 8
                    for (int d = 0; d < DDIM; d++) {
                        double xv = xp[d];
                        double t1 = xv - (double)e1p[d];
                        double t2 = xv - (double)e2p[d];
                        d1 += t1 * t1; d2 += t2 * t2;
                    }
                    if (d2 < d1 || (d2 == d1 && i2 < i1)) { i1 = i2; contrib = (float)d2; }
                    else contrib = (float)d1;
                }
                lsum += contrib;
                if (s) i1_1 = i1; else i1_0 = i1;
                if (out_size >= NTOT + 1 + NVEC)
                    out[NTOT + 1 + row] = (float)i1;
            }
        }

        // quantized gather/write: lane handles row (lane&15), half (lane>>4)
        {
            const int r    = lane & 15;
            const int half = lane >> 4;
            int src  = 4 * (r & 7);
            int from0 = __shfl_sync(0xffffffffu, i1_0, src);
            int from1 = __shfl_sync(0xffffffffu, i1_1, src);
            const int b = (r < 8) ? from0 : from1;
            const float4* ep = (const float4*)(embed + (size_t)b * DDIM + half * 32);
            float4* op = (float4*)(out + ((size_t)u * NROWS + r) * DDIM + half * 32);
#pragma unroll
            for (int i = 0; i < 8; i++) op[i] = ep[i];
        }
    }

    // ---- loss reduce -> global
    double ls = (double)lsum;
#pragma unroll
    for (int off = 16; off > 0; off >>= 1)
        ls += __shfl_down_sync(0xffffffffu, ls, off);
    if (lane == 0) atomicAdd(&g_loss, ls);

    __syncthreads();
    if (tid == 0) {
        __threadfence();
        unsigned done = atomicAdd(&g_done, 1u);
        if (done == GRID - 1) {
            unsigned long long bits =
                atomicExch((unsigned long long*)&g_loss, 0ull);
            double total = __longlong_as_double((long long)bits);
            if (out_size >= NTOT + 1)
                out[NTOT] = (float)(2.0 * total / (double)NTOT);
            atomicExch(&g_unit, 0u);
            atomicExch(&g_done, 0u);
        }
    }
}

extern "C" void kernel_launch(void* const* d_in, const int* in_sizes, int n_in,
                              void* d_out, int out_size) {
    const float* enc   = (const float*)d_in[0];
    const float* embed = (const float*)d_in[1];
    float* out = (float*)d_out;

    static bool attr_set = false;
    if (!attr_set) {
        cudaFuncSetAttribute(vq_mma_kernel,
                             cudaFuncAttributeMaxDynamicSharedMemorySize,
                             SMEM_TOTAL);
        attr_set = true;
    }

    vq_mma_kernel<<<GRID, TPB, SMEM_TOTAL>>>(enc, embed, out, out_size);
}

// round 12
// speedup vs baseline: 2.3600x; 1.1774x over previous
#include <cuda_runtime.h>
#include <cuda_fp16.h>
#include <cfloat>
#include <cstdint>

// Shapes: enc (32,64,64,64) fp32 -> 131072 vectors D=64; codebook (512,64) fp32.
#define DDIM    64
#define KCODE   512
#define NTOT    8388608
#define NVEC    131072
#define TPB     512
#define GRID    148
#define NROWS   16                 // rows per warp work unit
#define NUNITS  (NVEC / NROWS)     // 8192

// SMEM: B fragments (512 codes x 256B: h|m interleaved) + esq
#define B_BYTES   (KCODE * 256)          // 131072
#define ESQ_OFF   B_BYTES
#define SMEM_TOTAL (ESQ_OFF + 2048)      // 133120

__device__ double       g_loss = 0.0;
__device__ unsigned int g_unit = 0;
__device__ unsigned int g_done = 0;

__device__ __forceinline__ void mma_f16(float c[4], const unsigned a[4],
                                        unsigned b0, unsigned b1) {
    asm volatile(
        "mma.sync.aligned.m16n8k16.row.col.f32.f16.f16.f32 "
        "{%0,%1,%2,%3}, {%4,%5,%6,%7}, {%8,%9}, {%0,%1,%2,%3};"
        : "+f"(c[0]), "+f"(c[1]), "+f"(c[2]), "+f"(c[3])
        : "r"(a[0]), "r"(a[1]), "r"(a[2]), "r"(a[3]), "r"(b0), "r"(b1));
}

// fp32 -> 2x fp16 split: h+m == f up to ~2^-24 rel (residual covered by recheck)
__device__ __forceinline__ void split2(float f, unsigned short& h, unsigned short& m) {
    __half hh = __float2half_rn(f);
    float r = f - __half2float(hh);
    __half hm = __float2half_rn(r);
    h = __half_as_ushort(hh);
    m = __half_as_ushort(hm);
}
__device__ __forceinline__ unsigned pk(unsigned short a, unsigned short b) {
    return (unsigned)a | ((unsigned)b << 16);
}

// monotone fp32 -> u32 key, low 9 bits replaced by code index
__device__ __forceinline__ unsigned dkey(float f, int code) {
    unsigned bits = __float_as_uint(f);
    unsigned msk = (unsigned)(((int)bits) >> 31);
    unsigned sk = bits ^ (msk | 0x80000000u);
    return (sk & 0xFFFFFE00u) | (unsigned)code;
}
// merge two (b1,b2) top-2 key pairs
__device__ __forceinline__ void mrg2(unsigned& a1, unsigned& a2,
                                     unsigned b1, unsigned b2) {
    unsigned t = umax(a1, b1);
    a1 = umin(a1, b1);
    a2 = umin(t, umin(a2, b2));
}

__global__ __launch_bounds__(TPB, 1)
void vq_mma_kernel(const float* __restrict__ enc,
                   const float* __restrict__ embed,
                   float* __restrict__ out,
                   int out_size) {
    extern __shared__ unsigned char sraw[];
    float* s_esq = (float*)(sraw + ESQ_OFF);

    const int tid  = threadIdx.x;
    const int lane = tid & 31;
    const int rq   = lane >> 2;   // row-in-group 0..7
    const int q    = lane & 3;    // col-group 0..3

    // ---- one-time: codebook -> interleaved h|m fragment SMEM (-2*e) + esq
    // layout: code n at n*256; unit (ks,qq) at ((ks+n)&3)*64 + qq*16 = {h2lo,h2hi,m2lo,m2hi}
    for (int n = tid; n < KCODE; n += TPB) {
        const float4* g4 = (const float4*)(embed + (size_t)n * DDIM);
        float esq = 0.f;
        unsigned char* brow = sraw + (size_t)n * 256;
#pragma unroll
        for (int ks = 0; ks < 4; ks++) {
            float f[16];
#pragma unroll
            for (int i = 0; i < 4; i++) {
                float4 t = g4[ks * 4 + i];
                f[4*i+0] = t.x; f[4*i+1] = t.y; f[4*i+2] = t.z; f[4*i+3] = t.w;
            }
            unsigned short h[16], m[16];
#pragma unroll
            for (int i = 0; i < 16; i++) {
                esq += f[i] * f[i];
                split2(-2.0f * f[i], h[i], m[i]);
            }
            unsigned rot = ((unsigned)(ks + n) & 3u) * 64u;
#pragma unroll
            for (int qq = 0; qq < 4; qq++) {
                int k0 = 2 * qq;
                *(uint4*)(brow + rot + qq * 16) =
                    make_uint4(pk(h[k0], h[k0+1]), pk(h[k0+8], h[k0+9]),
                               pk(m[k0], m[k0+1]), pk(m[k0+8], m[k0+9]));
            }
        }
        s_esq[n] = esq;
    }
    __syncthreads();

    float lsum = 0.f;

    // ---- per-warp persistent work-stealing over 16-row units
    for (;;) {
        unsigned u;
        if (lane == 0) u = atomicAdd(&g_unit, 1u);
        u = __shfl_sync(0xffffffffu, u, 0);
        if (u >= NUNITS) break;

        // ---- A fragments: rows r0 = u*16 + rq, r1 = r0 + 8
        unsigned aF[2][4][4];   // [term h/m][kstep][reg]
        {
            const float* p0 = enc + ((size_t)u * NROWS + rq) * DDIM;
            const float* p1 = p0 + 8 * DDIM;
#pragma unroll
            for (int ks = 0; ks < 4; ks++) {
                const int c0 = 16 * ks + 2 * q;
                float2 x0a = *(const float2*)(p0 + c0);
                float2 x0b = *(const float2*)(p0 + c0 + 8);
                float2 x1a = *(const float2*)(p1 + c0);
                float2 x1b = *(const float2*)(p1 + c0 + 8);
                unsigned short h0,m0, h1,m1;
                split2(x0a.x, h0, m0); split2(x0a.y, h1, m1);
                aF[0][ks][0] = pk(h0,h1); aF[1][ks][0] = pk(m0,m1);
                split2(x1a.x, h0, m0); split2(x1a.y, h1, m1);
                aF[0][ks][1] = pk(h0,h1); aF[1][ks][1] = pk(m0,m1);
                split2(x0b.x, h0, m0); split2(x0b.y, h1, m1);
                aF[0][ks][2] = pk(h0,h1); aF[1][ks][2] = pk(m0,m1);
                split2(x1b.x, h0, m0); split2(x1b.y, h1, m1);
                aF[0][ks][3] = pk(h0,h1); aF[1][ks][3] = pk(m0,m1);
            }
        }

        unsigned kb1_0 = 0xFFFFFFFFu, kb2_0 = 0xFFFFFFFFu;
        unsigned kb1_1 = 0xFFFFFFFFu, kb2_1 = 0xFFFFFFFFu;

#pragma unroll 1
        for (int chunk = 0; chunk < 8; chunk++) {
            float c[8][4];
#pragma unroll
            for (int nf = 0; nf < 8; nf++) {            // init C with ||e||^2
                int n0 = chunk * 64 + nf * 8 + 2 * q;
                float2 e2 = *(const float2*)(s_esq + n0);
                c[nf][0] = e2.x; c[nf][1] = e2.y;
                c[nf][2] = e2.x; c[nf][3] = e2.y;
            }
            // 3-term MMA: hh, hm, mh (one LDS.128 per nf per ks)
#pragma unroll
            for (int ks = 0; ks < 4; ks++) {
                const unsigned rot = (((unsigned)ks + (unsigned)rq) & 3u) * 64u;
                const unsigned char* bp =
                    sraw + ((size_t)(chunk * 64 + rq)) * 256 + rot + (unsigned)q * 16u;
#pragma unroll
                for (int nf = 0; nf < 8; nf++) {
                    uint4 b = *(const uint4*)(bp + nf * 2048);
                    mma_f16(c[nf], aF[0][ks], b.x, b.y);   // hh
                    mma_f16(c[nf], aF[0][ks], b.z, b.w);   // hm
                    mma_f16(c[nf], aF[1][ks], b.x, b.y);   // mh
                }
            }
            // packed-key top-2 trees (parallel IMNMX, no serial pred chains)
            unsigned l1[8], l2[8];
#pragma unroll
            for (int s = 0; s < 2; s++) {
#pragma unroll
                for (int nf = 0; nf < 8; nf++) {
                    int n0 = chunk * 64 + nf * 8 + 2 * q;
                    unsigned ka = dkey(c[nf][2*s],   n0);
                    unsigned kb = dkey(c[nf][2*s+1], n0 + 1);
                    l1[nf] = umin(ka, kb);
                    l2[nf] = umax(ka, kb);
                }
#pragma unroll
                for (int w = 4; w > 0; w >>= 1)
#pragma unroll
                    for (int i = 0; i < 8; i++)
                        if (i < w) mrg2(l1[i], l2[i], l1[i + w], l2[i + w]);
                if (s == 0) mrg2(kb1_0, kb2_0, l1[0], l2[0]);
                else        mrg2(kb1_1, kb2_1, l1[0], l2[0]);
            }
        }

        // ---- merge top-2 across the 4 lanes sharing rows
#pragma unroll
        for (int off = 1; off <= 2; off <<= 1) {
            unsigned o1 = __shfl_xor_sync(0xffffffffu, kb1_0, off);
            unsigned o2 = __shfl_xor_sync(0xffffffffu, kb2_0, off);
            mrg2(kb1_0, kb2_0, o1, o2);
            o1 = __shfl_xor_sync(0xffffffffu, kb1_1, off);
            o2 = __shfl_xor_sync(0xffffffffu, kb2_1, off);
            mrg2(kb1_1, kb2_1, o1, o2);
        }

        int i1_0 = (int)(kb1_0 & 0x1FFu);
        int i1_1 = (int)(kb1_1 & 0x1FFu);

        if (q == 0) {
            // ---- exact recheck when key gap <= 1 quantum (covers trunc + dropped terms)
            const int row0 = (int)u * NROWS + rq;
#pragma unroll
            for (int s = 0; s < 2; s++) {
                unsigned k1 = s ? kb1_1 : kb1_0, k2 = s ? kb2_1 : kb2_0;
                if ((k2 >> 9) - (k1 >> 9) <= 1u) {
                    int i1 = (int)(k1 & 0x1FFu), i2 = (int)(k2 & 0x1FFu);
                    const float* xp  = enc + (size_t)(row0 + 8 * s) * DDIM;
                    const float* e1p = embed + (size_t)i1 * DDIM;
                    const float* e2p = embed + (size_t)i2 * DDIM;
                    double d1 = 0.0, d2 = 0.0;
#pragma unroll 8
                    for (int d = 0; d < DDIM; d++) {
                        double xv = xp[d];
                        double t1 = xv - (double)e1p[d];
                        double t2 = xv - (double)e2p[d];
                        d1 += t1 * t1; d2 += t2 * t2;
                    }
                    int pick = (d2 < d1 || (d2 == d1 && i2 < i1)) ? i2 : i1;
                    if (s) i1_1 = pick; else i1_0 = pick;
                }
            }
            if (out_size >= NTOT + 1 + NVEC) {
                out[NTOT + 1 + row0]     = (float)i1_0;
                out[NTOT + 1 + row0 + 8] = (float)i1_1;
            }
        }

        // ---- gather + write quantized + EXACT loss (all lanes):
        // lane handles row (lane&15), half (lane>>4); reads e and x, sums (e-x)^2
        {
            const int r    = lane & 15;
            const int half = lane >> 4;
            int src  = 4 * (r & 7);
            int from0 = __shfl_sync(0xffffffffu, i1_0, src);
            int from1 = __shfl_sync(0xffffffffu, i1_1, src);
            const int b = (r < 8) ? from0 : from1;
            const float4* ep = (const float4*)(embed + (size_t)b * DDIM + half * 32);
            const float4* xp = (const float4*)(enc +
                               ((size_t)u * NROWS + r) * DDIM + half * 32);
            float4* op = (float4*)(out + ((size_t)u * NROWS + r) * DDIM + half * 32);
#pragma unroll
            for (int i = 0; i < 8; i++) {
                float4 e = ep[i];
                float4 x = xp[i];
                float d0 = e.x - x.x, d1 = e.y - x.y, d2 = e.z - x.z, d3 = e.w - x.w;
                lsum += d0 * d0 + d1 * d1 + d2 * d2 + d3 * d3;
                op[i] = e;
            }
        }
    }

    // ---- loss reduce -> global
    double ls = (double)lsum;
#pragma unroll
    for (int off = 16; off > 0; off >>= 1)
        ls += __shfl_down_sync(0xffffffffu, ls, off);
    if (lane == 0) atomicAdd(&g_loss, ls);

    __syncthreads();
    if (tid == 0) {
        __threadfence();
        unsigned done = atomicAdd(&g_done, 1u);
        if (done == GRID - 1) {
            unsigned long long bits =
                atomicExch((unsigned long long*)&g_loss, 0ull);
            double total = __longlong_as_double((long long)bits);
            if (out_size >= NTOT + 1)
                out[NTOT] = (float)(2.0 * total / (double)NTOT);
            atomicExch(&g_unit, 0u);
            atomicExch(&g_done, 0u);
        }
    }
}

extern "C" void kernel_launch(void* const* d_in, const int* in_sizes, int n_in,
                              void* d_out, int out_size) {
    const float* enc   = (const float*)d_in[0];
    const float* embed = (const float*)d_in[1];
    float* out = (float*)d_out;

    static bool attr_set = false;
    if (!attr_set) {
        cudaFuncSetAttribute(vq_mma_kernel,
                             cudaFuncAttributeMaxDynamicSharedMemorySize,
                             SMEM_TOTAL);
        attr_set = true;
    }

    vq_mma_kernel<<<GRID, TPB, SMEM_TOTAL>>>(enc, embed, out, out_size);
}